// round 13
// baseline (speedup 1.0000x reference)
#include <cuda_runtime.h>
#include <math.h>
#include <stdint.h>

// Problem constants (LMUCell: B=32, T=2048, D=128, U=512, N=256)
#define Bsz  32
#define Tn   2048
#define Dn   128
#define Un   512
#define Nn   256
#define KTOT 896     // D + U + N  (fused input length)
#define OTOT 768     // U + N      (fused output length)
#define GRID 128     // persistent CTAs (<= SM count -> co-resident)
#define TPB  256
#define OPC  6       // outputs per CTA: 128*6 = 768

// ---------------- device scratch (static, no allocation) ----------------
__device__ float g_W1[Nn * Un];                     // (I+AT) @ Wmh
__device__ float g_w2[Un];                          // BT @ Wmh
__device__ float g_WT[OTOT * KTOT];                 // WbigT[u][k]  (row-major, k contiguous)
__device__ __align__(16) float g_state[2][8 * OTOT * 4]; // [buf][bq][k(768)][b(4)]
__device__ unsigned g_count;

// ---------------- f32x2 helpers ----------------
__device__ __forceinline__ unsigned long long splat2(float a) {
    unsigned long long r; unsigned au = __float_as_uint(a);
    asm("mov.b64 %0,{%1,%1};" : "=l"(r) : "r"(au));
    return r;
}
__device__ __forceinline__ void fma2(unsigned long long& d, unsigned long long a, unsigned long long b) {
    asm("fma.rn.f32x2 %0,%1,%2,%0;" : "+l"(d) : "l"(a), "l"(b));
}
__device__ __forceinline__ unsigned long long add2(unsigned long long a, unsigned long long b) {
    unsigned long long r;
    asm("add.rn.f32x2 %0,%1,%2;" : "=l"(r) : "l"(a), "l"(b));
    return r;
}
__device__ __forceinline__ void unpack2(unsigned long long v, float& lo, float& hi) {
    unsigned a, b;
    asm("mov.b64 {%0,%1},%2;" : "=r"(a), "=r"(b) : "l"(v));
    lo = __uint_as_float(a); hi = __uint_as_float(b);
}

// ---------------- init1: W1, w2, state init, barrier reset ----------------
__global__ void lmu_init1(const float* __restrict__ h0, const float* __restrict__ m0,
                          const float* __restrict__ Wmh, const float* __restrict__ AT,
                          const float* __restrict__ BT) {
    int i = blockIdx.x * blockDim.x + threadIdx.x;
    if (i < Nn * Un) {
        int j = i / Un, u = i % Un;                 // warp: same j, consecutive u -> coalesced Wmh
        float s = 0.f;
        #pragma unroll 4
        for (int q = 0; q < Nn; q++) {
            float a = AT[j * Nn + q] + (q == j ? 1.0f : 0.0f);
            s = fmaf(a, Wmh[q * Un + u], s);
        }
        g_W1[i] = s;
    } else if (i < Nn * Un + Un) {
        int u = i - Nn * Un;
        float s = 0.f;
        #pragma unroll 4
        for (int q = 0; q < Nn; q++) s = fmaf(BT[q], Wmh[q * Un + u], s);
        g_w2[u] = s;
    } else if (i < Nn * Un + Un + 8 * OTOT * 4) {
        int r = i - (Nn * Un + Un);
        int b  = r & 3;
        int k  = (r >> 2) % OTOT;
        int bq = r / (OTOT * 4);
        int gb = bq * 4 + b;
        g_state[0][r] = (k < Un) ? h0[gb * Un + k] : m0[gb * Nn + (k - Un)];
    } else if (i == Nn * Un + Un + 8 * OTOT * 4) {
        g_count = 0u;
    }
}

// ---------------- init2: build fused WbigT[u][k] ----------------
// z[b][u] = sum_k act[k] * WbigT[u][k],  act = [x_t(128) | h(512) | m(256)]
__global__ void lmu_init2(const float* __restrict__ ie, const float* __restrict__ he,
                          const float* __restrict__ me, const float* __restrict__ Wi,
                          const float* __restrict__ Whh, const float* __restrict__ AT,
                          const float* __restrict__ BT) {
    int i = blockIdx.x * blockDim.x + threadIdx.x;
    if (i >= OTOT * KTOT) return;
    int u = i / KTOT, k = i % KTOT;
    float v;
    if (u < Un) {                                   // h-output columns
        float w2u = g_w2[u];
        if (k < Dn)            v = fmaf(ie[k], w2u, Wi[k * Un + u]);
        else if (k < Dn + Un) { int kk = k - Dn; v = fmaf(he[kk], w2u, Whh[kk * Un + u]); }
        else                  { int j  = k - Dn - Un; v = fmaf(me[j], w2u, g_W1[j * Un + u]); }
    } else {                                        // m-output columns
        int n = u - Un; float btn = BT[n];
        if (k < Dn)            v = ie[k] * btn;
        else if (k < Dn + Un)  v = he[k - Dn] * btn;
        else { int j = k - Dn - Un; v = AT[j * Nn + n] + (j == n ? 1.0f : 0.0f) + me[j] * btn; }
    }
    g_WT[i] = v;
}

// ---------------- main persistent recurrence kernel ----------------
__global__ void __launch_bounds__(TPB) lmu_main(const float* __restrict__ x,
                                                float* __restrict__ out) {
    // Weight slice: 3 output-pairs, packed float2 per k, in SMEM (loaded once).
    __shared__ unsigned long long sW[3 * KTOT];

    const int tid   = threadIdx.x;
    const int c     = blockIdx.x;
    const int obase = c * OPC;

    for (int idx = tid; idx < 3 * KTOT; idx += TPB) {
        int p = idx / KTOT, k = idx % KTOT;
        unsigned w0 = __float_as_uint(g_WT[(obase + 2 * p)     * KTOT + k]);
        unsigned w1 = __float_as_uint(g_WT[(obase + 2 * p + 1) * KTOT + k]);
        unsigned long long pk;
        asm("mov.b64 %0,{%1,%2};" : "=l"(pk) : "r"(w0), "r"(w1));
        sW[idx] = pk;
    }
    __syncthreads();

    const int warp = tid >> 5, lane = tid & 31;
    const int bq = warp;                         // batch quad id (0..7)
    const float* xb = x + (size_t)(bq * 4) * (Tn * Dn);

    for (int t = 0; t < Tn; t++) {
        const float4* st = (const float4*)&g_state[t & 1][bq * OTOT * 4];

        unsigned long long acc[3][4];
        #pragma unroll
        for (int p = 0; p < 3; p++)
            #pragma unroll
            for (int b = 0; b < 4; b++) acc[p][b] = 0ull;

        // ---- x part: k = lane + 32*j, j = 0..3 ----
        #pragma unroll
        for (int j = 0; j < 4; j++) {
            int k = lane + 32 * j;
            unsigned long long a0 = splat2(xb[(0 * Tn + t) * Dn + k]);
            unsigned long long a1 = splat2(xb[(1 * Tn + t) * Dn + k]);
            unsigned long long a2 = splat2(xb[(2 * Tn + t) * Dn + k]);
            unsigned long long a3 = splat2(xb[(3 * Tn + t) * Dn + k]);
            #pragma unroll
            for (int p = 0; p < 3; p++) {
                unsigned long long w = sW[p * KTOT + k];
                fma2(acc[p][0], a0, w); fma2(acc[p][1], a1, w);
                fma2(acc[p][2], a2, w); fma2(acc[p][3], a3, w);
            }
        }

        // ---- state part: s = lane + 32*j, j = 0..23 ----
        #pragma unroll 8
        for (int j = 0; j < 24; j++) {
            int s = lane + 32 * j;
            float4 a = st[s];
            unsigned long long a0 = splat2(a.x), a1 = splat2(a.y);
            unsigned long long a2 = splat2(a.z), a3 = splat2(a.w);
            #pragma unroll
            for (int p = 0; p < 3; p++) {
                unsigned long long w = sW[p * KTOT + Dn + s];
                fma2(acc[p][0], a0, w); fma2(acc[p][1], a1, w);
                fma2(acc[p][2], a2, w); fma2(acc[p][3], a3, w);
            }
        }

        // ---- reduce partial sums across the 32 lanes (k-split) ----
        #pragma unroll
        for (int m = 16; m; m >>= 1) {
            #pragma unroll
            for (int p = 0; p < 3; p++)
                #pragma unroll
                for (int b = 0; b < 4; b++)
                    acc[p][b] = add2(acc[p][b], __shfl_xor_sync(0xffffffffu, acc[p][b], m));
        }

        // ---- write results (lanes 0..11: (pair, batch)) ----
        float* stout = &g_state[(t + 1) & 1][bq * OTOT * 4];
        if (lane < 12) {
            int p = lane >> 2, b = lane & 3;
            float v0, v1; unpack2(acc[p][b], v0, v1);
            int o0 = obase + 2 * p, o1 = o0 + 1;   // pairs never straddle u=512 (obase even)
            int gb = bq * 4 + b;
            if (o0 < Un) {
                v0 = tanhf(v0); v1 = tanhf(v1);
                out[((size_t)gb * Tn + t) * Un + o0] = v0;
                out[((size_t)gb * Tn + t) * Un + o1] = v1;
            }
            stout[o0 * 4 + b] = v0;
            stout[o1 * 4 + b] = v1;
        }

        // ---- grid barrier (all 128 CTAs co-resident) ----
        __threadfence();
        __syncthreads();
        if (tid == 0) {
            unsigned tgt = (unsigned)GRID * (unsigned)(t + 1);
            atomicAdd(&g_count, 1u);
            unsigned v;
            do {
                asm volatile("ld.global.acquire.gpu.u32 %0, [%1];" : "=r"(v) : "l"(&g_count));
            } while (v < tgt);
        }
        __syncthreads();
    }
}

// ---------------- launch ----------------
extern "C" void kernel_launch(void* const* d_in, const int* in_sizes, int n_in,
                              void* d_out, int out_size) {
    const float* x   = (const float*)d_in[0];   // (32,2048,128)
    const float* h0  = (const float*)d_in[1];   // (32,512)
    const float* m0  = (const float*)d_in[2];   // (32,256)
    const float* ie  = (const float*)d_in[3];   // (128,1)
    const float* he  = (const float*)d_in[4];   // (512,1)
    const float* me  = (const float*)d_in[5];   // (256,1)
    const float* Wi  = (const float*)d_in[6];   // (128,512)
    const float* Whh = (const float*)d_in[7];   // (512,512)
    const float* Wmh = (const float*)d_in[8];   // (256,512)
    const float* AT  = (const float*)d_in[9];   // (256,256)
    const float* BT  = (const float*)d_in[10];  // (1,256)
    float* out = (float*)d_out;                 // (32,2048,512)

    // init1: W1 = (I+AT)@Wmh, w2 = BT@Wmh, state[0] <- [h0|m0], barrier reset
    int n1 = Nn * Un + Un + 8 * OTOT * 4 + 1;
    lmu_init1<<<(n1 + TPB - 1) / TPB, TPB>>>(h0, m0, Wmh, AT, BT);

    // init2: fused big weight matrix (transposed, k-contiguous rows)
    int n2 = OTOT * KTOT;
    lmu_init2<<<(n2 + TPB - 1) / TPB, TPB>>>(ie, he, me, Wi, Whh, AT, BT);

    // persistent recurrence
    lmu_main<<<GRID, TPB>>>(x, out);
}

// round 14
// speedup vs baseline: 1.5475x; 1.5475x over previous
#include <cuda_runtime.h>
#include <math.h>
#include <stdint.h>

// Problem constants (LMUCell: B=32, T=2048, D=128, U=512, N=256)
#define Bsz  32
#define Tn   2048
#define Dn   128
#define Un   512
#define Nn   256
#define KTOT 896     // D + U + N  (fused input length)
#define OTOT 768     // U + N      (fused output length)
#define GRID 128     // persistent CTAs (one wave, distinct SMs)
#define TPB  256
#define COLS_CTA  24          // columns per CTA (12 f32x2 pairs)
#define PAIRS_CTA 12
#define SMEM_W_BYTES (PAIRS_CTA * KTOT * 8)   // 86016 B dynamic smem

// ---------------- device scratch (static, no allocation) ----------------
__device__ float g_W1[Nn * Un];                     // (I+AT) @ Wmh
__device__ float g_w2[Un];                          // BT @ Wmh
__device__ float g_WT[OTOT * KTOT];                 // WbigT[u][k]  (k contiguous)
__device__ __align__(16) float g_state[2][8 * OTOT * 4]; // [buf][bq][k(768)][b(4)]
__device__ unsigned g_arrive[GRID * 32];            // per-CTA flags, 128B apart

// ---------------- f32x2 helpers ----------------
__device__ __forceinline__ unsigned long long splat2(float a) {
    unsigned long long r; unsigned au = __float_as_uint(a);
    asm("mov.b64 %0,{%1,%1};" : "=l"(r) : "r"(au));
    return r;
}
__device__ __forceinline__ void fma2(unsigned long long& d, unsigned long long a, unsigned long long b) {
    asm("fma.rn.f32x2 %0,%1,%2,%0;" : "+l"(d) : "l"(a), "l"(b));
}
__device__ __forceinline__ unsigned long long add2(unsigned long long a, unsigned long long b) {
    unsigned long long r;
    asm("add.rn.f32x2 %0,%1,%2;" : "=l"(r) : "l"(a), "l"(b));
    return r;
}
__device__ __forceinline__ void unpack2(unsigned long long v, float& lo, float& hi) {
    unsigned a, b;
    asm("mov.b64 {%0,%1},%2;" : "=r"(a), "=r"(b) : "l"(v));
    lo = __uint_as_float(a); hi = __uint_as_float(b);
}

// ---------------- init1: W1, w2, state init, flag reset ----------------
__global__ void lmu_init1(const float* __restrict__ h0, const float* __restrict__ m0,
                          const float* __restrict__ Wmh, const float* __restrict__ AT,
                          const float* __restrict__ BT) {
    int i = blockIdx.x * blockDim.x + threadIdx.x;
    const int b1 = Nn * Un;
    const int b2 = b1 + Un;
    const int b3 = b2 + 8 * OTOT * 4;
    if (i < b1) {
        int j = i / Un, u = i % Un;
        float s = 0.f;
        #pragma unroll 4
        for (int q = 0; q < Nn; q++) {
            float a = AT[j * Nn + q] + (q == j ? 1.0f : 0.0f);
            s = fmaf(a, Wmh[q * Un + u], s);
        }
        g_W1[i] = s;
    } else if (i < b2) {
        int u = i - b1;
        float s = 0.f;
        #pragma unroll 4
        for (int q = 0; q < Nn; q++) s = fmaf(BT[q], Wmh[q * Un + u], s);
        g_w2[u] = s;
    } else if (i < b3) {
        int r = i - b2;
        int b  = r & 3;
        int k  = (r >> 2) % OTOT;
        int bq = r / (OTOT * 4);
        int gb = bq * 4 + b;
        g_state[0][r] = (k < Un) ? h0[gb * Un + k] : m0[gb * Nn + (k - Un)];
    } else if (i < b3 + GRID) {
        g_arrive[(i - b3) * 32] = 0u;   // reset barrier flags (graph replays!)
    }
}

// ---------------- init2: build fused WbigT[u][k] ----------------
// z[b][u] = sum_k act[k] * WbigT[u][k],  act = [x_t(128) | h(512) | m(256)]
__global__ void lmu_init2(const float* __restrict__ ie, const float* __restrict__ he,
                          const float* __restrict__ me, const float* __restrict__ Wi,
                          const float* __restrict__ Whh, const float* __restrict__ AT,
                          const float* __restrict__ BT) {
    int i = blockIdx.x * blockDim.x + threadIdx.x;
    if (i >= OTOT * KTOT) return;
    int u = i / KTOT, k = i % KTOT;
    float v;
    if (u < Un) {                                   // h-output columns
        float w2u = g_w2[u];
        if (k < Dn)            v = fmaf(ie[k], w2u, Wi[k * Un + u]);
        else if (k < Dn + Un) { int kk = k - Dn; v = fmaf(he[kk], w2u, Whh[kk * Un + u]); }
        else                  { int j  = k - Dn - Un; v = fmaf(me[j], w2u, g_W1[j * Un + u]); }
    } else {                                        // m-output columns
        int n = u - Un; float btn = BT[n];
        if (k < Dn)            v = ie[k] * btn;
        else if (k < Dn + Un)  v = he[k - Dn] * btn;
        else { int j = k - Dn - Un; v = AT[j * Nn + n] + (j == n ? 1.0f : 0.0f) + me[j] * btn; }
    }
    g_WT[i] = v;
}

// ---------------- main persistent recurrence kernel ----------------
extern __shared__ unsigned long long sW[];          // 12 pairs x 896 k (86 KB)

__global__ void __launch_bounds__(TPB, 1) lmu_main(const float* __restrict__ x,
                                                   float* __restrict__ out) {
    const int tid = threadIdx.x;
    const int c   = blockIdx.x;
    const int cg  = c & 31;               // column group 0..31
    const int bg  = c >> 5;               // batch group 0..3
    const int obase = cg * COLS_CTA;

    // Load this CTA's 24 weight columns as 12 packed pairs into SMEM (once).
    for (int idx = tid; idx < PAIRS_CTA * KTOT; idx += TPB) {
        int pp = idx / KTOT, k = idx % KTOT;
        unsigned w0 = __float_as_uint(g_WT[(obase + 2 * pp)     * KTOT + k]);
        unsigned w1 = __float_as_uint(g_WT[(obase + 2 * pp + 1) * KTOT + k]);
        unsigned long long pk;
        asm("mov.b64 %0,{%1,%2};" : "=l"(pk) : "r"(w0), "r"(w1));
        sW[idx] = pk;
    }
    __syncthreads();

    const int warp = tid >> 5, lane = tid & 31;
    const int pb  = warp >> 1;            // pair-block 0..3 (3 pairs each)
    const int bq  = warp & 1;             // local batch quad
    const int gbq = bg * 2 + bq;          // global batch quad 0..7
    const float* xb = x + (size_t)(gbq * 4) * (Tn * Dn);
    const unsigned long long* wp = &sW[(pb * 3) * KTOT];

    // Prefetch x for t = 0
    float xr[16];
    #pragma unroll
    for (int j = 0; j < 4; j++) {
        int k = lane + 32 * j;
        #pragma unroll
        for (int b = 0; b < 4; b++)
            xr[j * 4 + b] = xb[((size_t)b * Tn) * Dn + k];
    }

    for (int t = 0; t < Tn; t++) {
        const float4* st = (const float4*)&g_state[t & 1][gbq * OTOT * 4];

        unsigned long long acc[3][4];
        #pragma unroll
        for (int p = 0; p < 3; p++)
            #pragma unroll
            for (int b = 0; b < 4; b++) acc[p][b] = 0ull;

        // ---- x part (prefetched): k = lane + 32j, j = 0..3 ----
        #pragma unroll
        for (int j = 0; j < 4; j++) {
            int k = lane + 32 * j;
            unsigned long long a0 = splat2(xr[j * 4 + 0]);
            unsigned long long a1 = splat2(xr[j * 4 + 1]);
            unsigned long long a2 = splat2(xr[j * 4 + 2]);
            unsigned long long a3 = splat2(xr[j * 4 + 3]);
            #pragma unroll
            for (int p = 0; p < 3; p++) {
                unsigned long long w = wp[p * KTOT + k];
                fma2(acc[p][0], a0, w); fma2(acc[p][1], a1, w);
                fma2(acc[p][2], a2, w); fma2(acc[p][3], a3, w);
            }
        }

        // ---- state part: s = lane + 32j, j = 0..23 ----
        #pragma unroll 8
        for (int j = 0; j < 24; j++) {
            int s = lane + 32 * j;
            float4 a = st[s];
            unsigned long long a0 = splat2(a.x), a1 = splat2(a.y);
            unsigned long long a2 = splat2(a.z), a3 = splat2(a.w);
            #pragma unroll
            for (int p = 0; p < 3; p++) {
                unsigned long long w = wp[p * KTOT + Dn + s];
                fma2(acc[p][0], a0, w); fma2(acc[p][1], a1, w);
                fma2(acc[p][2], a2, w); fma2(acc[p][3], a3, w);
            }
        }

        // ---- reduce partials across 32 lanes (k-split) ----
        #pragma unroll
        for (int m = 16; m; m >>= 1) {
            #pragma unroll
            for (int p = 0; p < 3; p++)
                #pragma unroll
                for (int b = 0; b < 4; b++)
                    acc[p][b] = add2(acc[p][b], __shfl_xor_sync(0xffffffffu, acc[p][b], m));
        }

        // ---- write new state (lanes 0..11: (pair, batch)) ----
        float* stout = &g_state[(t + 1) & 1][gbq * OTOT * 4];
        float v0 = 0.f, v1 = 0.f;
        int o0 = 0;
        bool isH = false;
        if (lane < 12) {
            int p = lane >> 2, b = lane & 3;
            unpack2(acc[p][b], v0, v1);
            o0 = obase + (pb * 3 + p) * 2;      // even; pairs never straddle u=512
            isH = (o0 < Un);
            if (isH) { v0 = tanhf(v0); v1 = tanhf(v1); }
            stout[o0 * 4 + b]       = v0;
            stout[(o0 + 1) * 4 + b] = v1;
        }

        // ---- arrive: state writes visible, then flag (release) ----
        __syncthreads();
        if (tid == 0) {
            asm volatile("st.global.release.gpu.u32 [%0], %1;"
                         :: "l"(&g_arrive[c * 32]), "r"((unsigned)(t + 1)) : "memory");
        }

        // ---- hide latency behind the barrier: prefetch x(t+1), write out ----
        int tn = (t + 1 < Tn) ? (t + 1) : t;
        #pragma unroll
        for (int j = 0; j < 4; j++) {
            int k = lane + 32 * j;
            #pragma unroll
            for (int b = 0; b < 4; b++)
                xr[j * 4 + b] = xb[((size_t)b * Tn + tn) * Dn + k];
        }
        if (isH) {
            int b = lane & 3;
            size_t base = ((size_t)(gbq * 4 + b) * Tn + t) * Un;
            out[base + o0]     = v0;
            out[base + o0 + 1] = v1;
        }

        // ---- wait: all 128 flags >= t+1 (distinct lines, one thread each) ----
        if (t + 1 < Tn) {
            if (tid < GRID) {
                const unsigned* fp = &g_arrive[tid * 32];
                unsigned v;
                do {
                    asm volatile("ld.global.acquire.gpu.u32 %0, [%1];" : "=r"(v) : "l"(fp));
                } while (v < (unsigned)(t + 1));
            }
            __syncthreads();
        }
    }
}

// ---------------- launch ----------------
extern "C" void kernel_launch(void* const* d_in, const int* in_sizes, int n_in,
                              void* d_out, int out_size) {
    const float* x   = (const float*)d_in[0];   // (32,2048,128)
    const float* h0  = (const float*)d_in[1];   // (32,512)
    const float* m0  = (const float*)d_in[2];   // (32,256)
    const float* ie  = (const float*)d_in[3];   // (128,1)
    const float* he  = (const float*)d_in[4];   // (512,1)
    const float* me  = (const float*)d_in[5];   // (256,1)
    const float* Wi  = (const float*)d_in[6];   // (128,512)
    const float* Whh = (const float*)d_in[7];   // (512,512)
    const float* Wmh = (const float*)d_in[8];   // (256,512)
    const float* AT  = (const float*)d_in[9];   // (256,256)
    const float* BT  = (const float*)d_in[10];  // (1,256)
    float* out = (float*)d_out;                 // (32,2048,512)

    cudaFuncSetAttribute(lmu_main, cudaFuncAttributeMaxDynamicSharedMemorySize,
                         SMEM_W_BYTES);

    // init1: W1 = (I+AT)@Wmh, w2 = BT@Wmh, state[0] <- [h0|m0], flags reset
    int n1 = Nn * Un + Un + 8 * OTOT * 4 + GRID;
    lmu_init1<<<(n1 + TPB - 1) / TPB, TPB>>>(h0, m0, Wmh, AT, BT);

    // init2: fused big weight matrix (transposed, k-contiguous rows)
    int n2 = OTOT * KTOT;
    lmu_init2<<<(n2 + TPB - 1) / TPB, TPB>>>(ie, he, me, Wi, Whh, AT, BT);

    // persistent recurrence
    lmu_main<<<GRID, TPB, SMEM_W_BYTES>>>(x, out);
}